// round 9
// baseline (speedup 1.0000x reference)
#include <cuda_runtime.h>
#include <cuda_bf16.h>
#include <cstdint>

// out[s,b,d] = x[s,b,0]*W_xy[d,0] + x[s,b,1]*W_xy[d,1]
//            + x[s,b,2]*W_seg[d] + b_xy[d] + b_seg[d] + pe[s,d]
//
// S=256, B=256, D=1024 fp32 -> 268 MB output, DRAM-write-bound
// (demonstrated 5.68 TB/s sustained across 7 kernel structures).
//
// R9: R1's tiled structure with 256-bit stores (st.global.v8.b32) —
// the last untested store-path variable. Each thread owns 8 consecutive
// d-floats; 256 threads cover 2 rows/iteration; 16 iterations per block.

#define S_DIM 256
#define B_DIM 256
#define D_DIM 1024
#define B_PER_BLK 32
#define CHUNKS (B_DIM / B_PER_BLK)   // 8 chunks per s

__device__ __forceinline__ void st256(float* p, const float* v) {
    asm volatile(
        "st.global.v8.b32 [%0], {%1,%2,%3,%4,%5,%6,%7,%8};"
        :: "l"(p),
           "r"(__float_as_uint(v[0])), "r"(__float_as_uint(v[1])),
           "r"(__float_as_uint(v[2])), "r"(__float_as_uint(v[3])),
           "r"(__float_as_uint(v[4])), "r"(__float_as_uint(v[5])),
           "r"(__float_as_uint(v[6])), "r"(__float_as_uint(v[7]))
        : "memory");
}

__global__ __launch_bounds__(256, 4)
void pe_fused_kernel(const float* __restrict__ x,
                     const float* __restrict__ Wxy,
                     const float* __restrict__ bxy,
                     const float* __restrict__ Wseg,
                     const float* __restrict__ bseg,
                     const float* __restrict__ pe,
                     float* __restrict__ out)
{
    __shared__ float xs[B_PER_BLK * 3];

    const int s    = blockIdx.x >> 3;                 // / CHUNKS
    const int b0   = (blockIdx.x & (CHUNKS - 1)) * B_PER_BLK;
    const int half = threadIdx.x >> 7;                // row within each pair
    const int d    = (threadIdx.x & 127) << 3;        // 8-float d-slice

    // Stage x[s, b0 : b0+32, 0:3] (96 contiguous floats) into shared.
    if (threadIdx.x < B_PER_BLK * 3)
        xs[threadIdx.x] = x[(size_t)(s * B_DIM + b0) * 3 + threadIdx.x];

    // Block-lifetime coefficients for d..d+7.
    // W_xy [D,2] row-major: rows d..d+7 = 16 interleaved floats.
    const float4* W2 = reinterpret_cast<const float4*>(Wxy + d * 2);
    const float4 a0 = W2[0], a1 = W2[1], a2 = W2[2], a3 = W2[3];
    const float cw0[8] = {a0.x, a0.z, a1.x, a1.z, a2.x, a2.z, a3.x, a3.z};
    const float cw1[8] = {a0.y, a0.w, a1.y, a1.w, a2.y, a2.w, a3.y, a3.w};

    const float4 s0 = *reinterpret_cast<const float4*>(Wseg + d);
    const float4 s1 = *reinterpret_cast<const float4*>(Wseg + d + 4);
    const float cw2[8] = {s0.x, s0.y, s0.z, s0.w, s1.x, s1.y, s1.z, s1.w};

    const float4 ba0 = *reinterpret_cast<const float4*>(bxy + d);
    const float4 ba1 = *reinterpret_cast<const float4*>(bxy + d + 4);
    const float4 bb0 = *reinterpret_cast<const float4*>(bseg + d);
    const float4 bb1 = *reinterpret_cast<const float4*>(bseg + d + 4);
    const float4 p0  = *reinterpret_cast<const float4*>(pe + (size_t)s * D_DIM + d);
    const float4 p1  = *reinterpret_cast<const float4*>(pe + (size_t)s * D_DIM + d + 4);

    const float base[8] = {
        p0.x + ba0.x + bb0.x, p0.y + ba0.y + bb0.y,
        p0.z + ba0.z + bb0.z, p0.w + ba0.w + bb0.w,
        p1.x + ba1.x + bb1.x, p1.y + ba1.y + bb1.y,
        p1.z + ba1.z + bb1.z, p1.w + ba1.w + bb1.w
    };

    __syncthreads();

    float* o = out + (size_t)(s * B_DIM + b0 + half) * D_DIM + d;

    #pragma unroll 4
    for (int i = 0; i < B_PER_BLK / 2; ++i) {
        const int row = i * 2 + half;
        const float x0 = xs[row * 3 + 0];
        const float x1 = xs[row * 3 + 1];
        const float x2 = xs[row * 3 + 2];

        float v[8];
        #pragma unroll
        for (int j = 0; j < 8; ++j)
            v[j] = fmaf(x0, cw0[j], fmaf(x1, cw1[j], fmaf(x2, cw2[j], base[j])));

        st256(o + (size_t)(i * 2) * D_DIM, v);
    }
}

extern "C" void kernel_launch(void* const* d_in, const int* in_sizes, int n_in,
                              void* d_out, int out_size)
{
    const float* x    = (const float*)d_in[0];   // [S,B,3]
    const float* Wxy  = (const float*)d_in[1];   // [D,2]
    const float* bxy  = (const float*)d_in[2];   // [D]
    const float* Wseg = (const float*)d_in[3];   // [D,1]
    const float* bseg = (const float*)d_in[4];   // [D]
    const float* pe   = (const float*)d_in[5];   // [MAX_LEN,1,D]
    float* out = (float*)d_out;                  // [S,B,D]

    pe_fused_kernel<<<S_DIM * CHUNKS, 256>>>(x, Wxy, bxy, Wseg, bseg, pe, out);
}

// round 10
// speedup vs baseline: 1.1751x; 1.1751x over previous
#include <cuda_runtime.h>
#include <cuda_bf16.h>

// out[s,b,d] = x[s,b,0]*W_xy[d,0] + x[s,b,1]*W_xy[d,1]
//            + x[s,b,2]*W_seg[d] + b_xy[d] + b_seg[d] + pe[s,d]
//
// S=256, B=256, D=1024, fp32 output = 268 MB -> DRAM-write-bound.
//
// FINAL kernel (== R1; best of 8 tested structures at 46.7us =
// 5.74 TB/s sustained DRAM write, ~72% of HBM3e spec = the pure-write
// roofline). Falsified alternatives: persistent one-wave STG (47.6),
// __ldg broadcast (48.2), TMA bulk S2G (49.2), write-back stores (49.9),
// L2::evict_last cross-replay residency (47.9), STG.256 (70.4 — L1tex
// wavefront-bound). The limiter is DRAM write bandwidth, not structure.
//
// Structure: block = (s, 32 b-rows); 256 threads each own a d-float4.
// Prologue: stage x rows to smem once, fold all per-d coefficients +
// pe[s] + biases into registers. Steady state per row: 3 broadcast LDS
// + 12 FFMA + 1 STG.128 — stores are the only steady-state memory traffic.

#define S_DIM 256
#define B_DIM 256
#define D_DIM 1024
#define B_PER_BLK 32           // b values per block
#define CHUNKS (B_DIM / B_PER_BLK)   // 8 chunks per s

__global__ __launch_bounds__(256, 8)
void pe_fused_kernel(const float* __restrict__ x,
                     const float* __restrict__ Wxy,
                     const float* __restrict__ bxy,
                     const float* __restrict__ Wseg,
                     const float* __restrict__ bseg,
                     const float* __restrict__ pe,
                     float* __restrict__ out)
{
    __shared__ float xs[B_PER_BLK * 3];

    const int s  = blockIdx.x >> 3;          // / CHUNKS
    const int b0 = (blockIdx.x & (CHUNKS - 1)) * B_PER_BLK;
    const int d  = threadIdx.x << 2;         // float4 per thread covers D=1024

    // Stage x[s, b0 : b0+32, 0:3] (96 contiguous floats) into shared.
    if (threadIdx.x < B_PER_BLK * 3)
        xs[threadIdx.x] = x[(size_t)(s * B_DIM + b0) * 3 + threadIdx.x];

    // Per-d coefficients -> registers (block-lifetime, loaded once).
    // W_xy is [D,2] row-major: rows d..d+3 are 8 interleaved floats.
    const float4 w01 = *reinterpret_cast<const float4*>(Wxy + d * 2);
    const float4 w23 = *reinterpret_cast<const float4*>(Wxy + d * 2 + 4);
    const float4 c2  = *reinterpret_cast<const float4*>(Wseg + d);
    const float4 ba  = *reinterpret_cast<const float4*>(bxy + d);
    const float4 bs  = *reinterpret_cast<const float4*>(bseg + d);
    const float4 p   = *reinterpret_cast<const float4*>(pe + (size_t)s * D_DIM + d);

    const float c0x = w01.x, c1x = w01.y;   // d+0
    const float c0y = w01.z, c1y = w01.w;   // d+1
    const float c0z = w23.x, c1z = w23.y;   // d+2
    const float c0w = w23.z, c1w = w23.w;   // d+3

    float4 base;
    base.x = p.x + ba.x + bs.x;
    base.y = p.y + ba.y + bs.y;
    base.z = p.z + ba.z + bs.z;
    base.w = p.w + ba.w + bs.w;

    __syncthreads();

    float4* o = reinterpret_cast<float4*>(
        out + (size_t)(s * B_DIM + b0) * D_DIM + d);

    #pragma unroll 8
    for (int i = 0; i < B_PER_BLK; ++i) {
        const float x0 = xs[i * 3 + 0];
        const float x1 = xs[i * 3 + 1];
        const float x2 = xs[i * 3 + 2];
        float4 r;
        r.x = fmaf(x0, c0x, fmaf(x1, c1x, fmaf(x2, c2.x, base.x)));
        r.y = fmaf(x0, c0y, fmaf(x1, c1y, fmaf(x2, c2.y, base.y)));
        r.z = fmaf(x0, c0z, fmaf(x1, c1z, fmaf(x2, c2.z, base.z)));
        r.w = fmaf(x0, c0w, fmaf(x1, c1w, fmaf(x2, c2.w, base.w)));
        o[i * (D_DIM / 4)] = r;
    }
}

extern "C" void kernel_launch(void* const* d_in, const int* in_sizes, int n_in,
                              void* d_out, int out_size)
{
    const float* x    = (const float*)d_in[0];   // [S,B,3]
    const float* Wxy  = (const float*)d_in[1];   // [D,2]
    const float* bxy  = (const float*)d_in[2];   // [D]
    const float* Wseg = (const float*)d_in[3];   // [D,1]
    const float* bseg = (const float*)d_in[4];   // [D]
    const float* pe   = (const float*)d_in[5];   // [MAX_LEN,1,D]
    float* out = (float*)d_out;                  // [S,B,D]

    pe_fused_kernel<<<S_DIM * CHUNKS, 256>>>(x, Wxy, bxy, Wseg, bseg, pe, out);
}

// round 11
// speedup vs baseline: 1.5467x; 1.3162x over previous
#include <cuda_runtime.h>
#include <cuda_bf16.h>

// out[s,b,d] = x[s,b,0]*W_xy[d,0] + x[s,b,1]*W_xy[d,1]
//            + x[s,b,2]*W_seg[d] + b_xy[d] + b_seg[d] + pe[s,d]
//
// S=256, B=256, D=1024, fp32 output = 268 MB.
//
// R11: R1's tiled structure with the x-broadcast LDS vectorized.
// Observation: identical R1 source measured 47.2us and 59.9us across
// rounds; counter ratios (L1 62->77%, DRAM 58->44%) show SM-clock DVFS
// shifting the bottleneck into L1tex. Stores are already at the 4-
// wavefront/row floor; the 3 scalar LDS broadcasts per row were 3/7 of
// L1tex wavefronts. Loading x for 4 rows via 3x LDS.128 cuts per-row
// wavefronts 7 -> 4.75 (-32%), making the kernel clock-state-robust.

#define S_DIM 256
#define B_DIM 256
#define D_DIM 1024
#define B_PER_BLK 32           // b values per block
#define CHUNKS (B_DIM / B_PER_BLK)   // 8 chunks per s

__global__ __launch_bounds__(256, 8)
void pe_fused_kernel(const float* __restrict__ x,
                     const float* __restrict__ Wxy,
                     const float* __restrict__ bxy,
                     const float* __restrict__ Wseg,
                     const float* __restrict__ bseg,
                     const float* __restrict__ pe,
                     float* __restrict__ out)
{
    __shared__ __align__(16) float xs[B_PER_BLK * 3];   // 96 floats = 24 float4

    const int s  = blockIdx.x >> 3;          // / CHUNKS
    const int b0 = (blockIdx.x & (CHUNKS - 1)) * B_PER_BLK;
    const int d  = threadIdx.x << 2;         // float4 per thread covers D=1024

    // Stage x[s, b0 : b0+32, 0:3] (96 contiguous floats) into shared.
    if (threadIdx.x < B_PER_BLK * 3)
        xs[threadIdx.x] = x[(size_t)(s * B_DIM + b0) * 3 + threadIdx.x];

    // Per-d coefficients -> registers (block-lifetime, loaded once).
    // W_xy is [D,2] row-major: rows d..d+3 are 8 interleaved floats.
    const float4 w01 = *reinterpret_cast<const float4*>(Wxy + d * 2);
    const float4 w23 = *reinterpret_cast<const float4*>(Wxy + d * 2 + 4);
    const float4 c2  = *reinterpret_cast<const float4*>(Wseg + d);
    const float4 ba  = *reinterpret_cast<const float4*>(bxy + d);
    const float4 bs  = *reinterpret_cast<const float4*>(bseg + d);
    const float4 p   = *reinterpret_cast<const float4*>(pe + (size_t)s * D_DIM + d);

    const float c0x = w01.x, c1x = w01.y;   // d+0
    const float c0y = w01.z, c1y = w01.w;   // d+1
    const float c0z = w23.x, c1z = w23.y;   // d+2
    const float c0w = w23.z, c1w = w23.w;   // d+3

    float4 base;
    base.x = p.x + ba.x + bs.x;
    base.y = p.y + ba.y + bs.y;
    base.z = p.z + ba.z + bs.z;
    base.w = p.w + ba.w + bs.w;

    __syncthreads();

    float4* o = reinterpret_cast<float4*>(
        out + (size_t)(s * B_DIM + b0) * D_DIM + d);
    const float4* xs4 = reinterpret_cast<const float4*>(xs);

    // 8 groups of 4 rows; per group: 3 vector LDS.128 broadcasts supply the
    // 12 x-floats for 4 rows (was 12 scalar LDS).
    #pragma unroll
    for (int g = 0; g < B_PER_BLK / 4; ++g) {
        const float4 q0 = xs4[3 * g + 0];
        const float4 q1 = xs4[3 * g + 1];
        const float4 q2 = xs4[3 * g + 2];

        const float rx[4][3] = {
            {q0.x, q0.y, q0.z},     // row 4g+0
            {q0.w, q1.x, q1.y},     // row 4g+1
            {q1.z, q1.w, q2.x},     // row 4g+2
            {q2.y, q2.z, q2.w}      // row 4g+3
        };

        #pragma unroll
        for (int rsub = 0; rsub < 4; ++rsub) {
            const float x0 = rx[rsub][0];
            const float x1 = rx[rsub][1];
            const float x2 = rx[rsub][2];
            float4 v;
            v.x = fmaf(x0, c0x, fmaf(x1, c1x, fmaf(x2, c2.x, base.x)));
            v.y = fmaf(x0, c0y, fmaf(x1, c1y, fmaf(x2, c2.y, base.y)));
            v.z = fmaf(x0, c0z, fmaf(x1, c1z, fmaf(x2, c2.z, base.z)));
            v.w = fmaf(x0, c0w, fmaf(x1, c1w, fmaf(x2, c2.w, base.w)));
            o[(g * 4 + rsub) * (D_DIM / 4)] = v;
        }
    }
}

extern "C" void kernel_launch(void* const* d_in, const int* in_sizes, int n_in,
                              void* d_out, int out_size)
{
    const float* x    = (const float*)d_in[0];   // [S,B,3]
    const float* Wxy  = (const float*)d_in[1];   // [D,2]
    const float* bxy  = (const float*)d_in[2];   // [D]
    const float* Wseg = (const float*)d_in[3];   // [D,1]
    const float* bseg = (const float*)d_in[4];   // [D]
    const float* pe   = (const float*)d_in[5];   // [MAX_LEN,1,D]
    float* out = (float*)d_out;                  // [S,B,D]

    pe_fused_kernel<<<S_DIM * CHUNKS, 256>>>(x, Wxy, bxy, Wseg, bseg, pe, out);
}

// round 12
// speedup vs baseline: 1.6184x; 1.0463x over previous
#include <cuda_runtime.h>
#include <cuda_bf16.h>

// out[s,b,d] = x[s,b,0]*W_xy[d,0] + x[s,b,1]*W_xy[d,1]
//            + x[s,b,2]*W_seg[d] + b_xy[d] + b_seg[d] + pe[s,d]
//
// S=256, B=256, D=1024, fp32 output = 268 MB.
//
// R12 = R11 (grouped LDS.128 x-broadcast, 4.75 L1tex wavefronts/row --
// the proven 45.5us structure) with evict-first streaming stores (__stcs).
// Output lines are never re-read; evict-first keeps pe + coefficients
// L2-resident and gives the DRAM writeback scheduler a clean stream
// (R3 vs R5 measured stcs ~2us faster than write-back on this workload).

#define S_DIM 256
#define B_DIM 256
#define D_DIM 1024
#define B_PER_BLK 32           // b values per block
#define CHUNKS (B_DIM / B_PER_BLK)   // 8 chunks per s

__global__ __launch_bounds__(256, 8)
void pe_fused_kernel(const float* __restrict__ x,
                     const float* __restrict__ Wxy,
                     const float* __restrict__ bxy,
                     const float* __restrict__ Wseg,
                     const float* __restrict__ bseg,
                     const float* __restrict__ pe,
                     float* __restrict__ out)
{
    __shared__ __align__(16) float xs[B_PER_BLK * 3];   // 96 floats = 24 float4

    const int s  = blockIdx.x >> 3;          // / CHUNKS
    const int b0 = (blockIdx.x & (CHUNKS - 1)) * B_PER_BLK;
    const int d  = threadIdx.x << 2;         // float4 per thread covers D=1024

    // Stage x[s, b0 : b0+32, 0:3] (96 contiguous floats) into shared.
    if (threadIdx.x < B_PER_BLK * 3)
        xs[threadIdx.x] = x[(size_t)(s * B_DIM + b0) * 3 + threadIdx.x];

    // Per-d coefficients -> registers (block-lifetime, loaded once).
    // W_xy is [D,2] row-major: rows d..d+3 are 8 interleaved floats.
    const float4 w01 = *reinterpret_cast<const float4*>(Wxy + d * 2);
    const float4 w23 = *reinterpret_cast<const float4*>(Wxy + d * 2 + 4);
    const float4 c2  = *reinterpret_cast<const float4*>(Wseg + d);
    const float4 ba  = *reinterpret_cast<const float4*>(bxy + d);
    const float4 bs  = *reinterpret_cast<const float4*>(bseg + d);
    const float4 p   = *reinterpret_cast<const float4*>(pe + (size_t)s * D_DIM + d);

    const float c0x = w01.x, c1x = w01.y;   // d+0
    const float c0y = w01.z, c1y = w01.w;   // d+1
    const float c0z = w23.x, c1z = w23.y;   // d+2
    const float c0w = w23.z, c1w = w23.w;   // d+3

    float4 base;
    base.x = p.x + ba.x + bs.x;
    base.y = p.y + ba.y + bs.y;
    base.z = p.z + ba.z + bs.z;
    base.w = p.w + ba.w + bs.w;

    __syncthreads();

    float4* o = reinterpret_cast<float4*>(
        out + (size_t)(s * B_DIM + b0) * D_DIM + d);
    const float4* xs4 = reinterpret_cast<const float4*>(xs);

    // 8 groups of 4 rows; per group: 3 vector LDS.128 broadcasts supply the
    // 12 x-floats for 4 rows.
    #pragma unroll
    for (int g = 0; g < B_PER_BLK / 4; ++g) {
        const float4 q0 = xs4[3 * g + 0];
        const float4 q1 = xs4[3 * g + 1];
        const float4 q2 = xs4[3 * g + 2];

        const float rx[4][3] = {
            {q0.x, q0.y, q0.z},     // row 4g+0
            {q0.w, q1.x, q1.y},     // row 4g+1
            {q1.z, q1.w, q2.x},     // row 4g+2
            {q2.y, q2.z, q2.w}      // row 4g+3
        };

        #pragma unroll
        for (int rsub = 0; rsub < 4; ++rsub) {
            const float x0 = rx[rsub][0];
            const float x1 = rx[rsub][1];
            const float x2 = rx[rsub][2];
            float4 v;
            v.x = fmaf(x0, c0x, fmaf(x1, c1x, fmaf(x2, c2.x, base.x)));
            v.y = fmaf(x0, c0y, fmaf(x1, c1y, fmaf(x2, c2.y, base.y)));
            v.z = fmaf(x0, c0z, fmaf(x1, c1z, fmaf(x2, c2.z, base.z)));
            v.w = fmaf(x0, c0w, fmaf(x1, c1w, fmaf(x2, c2.w, base.w)));
            __stcs(o + (g * 4 + rsub) * (D_DIM / 4), v);   // evict-first stream
        }
    }
}

extern "C" void kernel_launch(void* const* d_in, const int* in_sizes, int n_in,
                              void* d_out, int out_size)
{
    const float* x    = (const float*)d_in[0];   // [S,B,3]
    const float* Wxy  = (const float*)d_in[1];   // [D,2]
    const float* bxy  = (const float*)d_in[2];   // [D]
    const float* Wseg = (const float*)d_in[3];   // [D,1]
    const float* bseg = (const float*)d_in[4];   // [D]
    const float* pe   = (const float*)d_in[5];   // [MAX_LEN,1,D]
    float* out = (float*)d_out;                  // [S,B,D]

    pe_fused_kernel<<<S_DIM * CHUNKS, 256>>>(x, Wxy, bxy, Wseg, bseg, pe, out);
}